// round 9
// baseline (speedup 1.0000x reference)
#include <cuda_runtime.h>
#include <cuda_bf16.h>

// ISTFT: B=8192, F=257 bins, T=6 frames, n_fft=512, hop=128, out len 600.
// CTA = 192 threads handles TWO batch elements (grid 4096). Each warp owns
// two frames (16 lanes each). irfft-512 = Hermitian half-size trick folded
// into staging -> 256-pt complex inverse FFT via four-step 16x16:
//   16-pt register IFFT (const twiddles) -> e^{i pi L k1/128} twiddle ->
//   16x16 transpose through shared (pitch 17) -> 16-pt register IFFT.
// No cross-lane shuffles at all. OLA on output pairs with analytic windows.

#define NT 192
#define PI_F 3.14159265358979323846f

#define BFLY0(i0,i1) { const float tr=Br[i1], ti=Bi[i1]; \
    Br[i1]=Br[i0]-tr; Bi[i1]=Bi[i0]-ti; Br[i0]+=tr; Bi[i0]+=ti; }
#define BFLYI(i0,i1) { const float tr=-Bi[i1], ti=Br[i1]; \
    Br[i1]=Br[i0]-tr; Bi[i1]=Bi[i0]-ti; Br[i0]+=tr; Bi[i0]+=ti; }
#define BFLYW(i0,i1,cr,ci) { \
    const float vr=Br[i1]*(cr)-Bi[i1]*(ci); \
    const float vi=Br[i1]*(ci)+Bi[i1]*(cr); \
    Br[i1]=Br[i0]-vr; Bi[i1]=Bi[i0]-vi; Br[i0]+=vr; Bi[i0]+=vi; }

// 16-pt inverse DIT FFT (input in bit-reversed slots, output natural order).
__device__ __forceinline__ void ifft16(float (&Br)[16], float (&Bi)[16]) {
    const float R  = 0.70710678118654752440f;   // cos(pi/4)
    const float C8 = 0.92387953251128675613f;   // cos(pi/8)
    const float S8 = 0.38268343236508977172f;   // sin(pi/8)
    BFLY0(0,1)  BFLY0(2,3)   BFLY0(4,5)  BFLY0(6,7)
    BFLY0(8,9)  BFLY0(10,11) BFLY0(12,13) BFLY0(14,15)
    BFLY0(0,2)  BFLYI(1,3)   BFLY0(4,6)  BFLYI(5,7)
    BFLY0(8,10) BFLYI(9,11)  BFLY0(12,14) BFLYI(13,15)
    BFLY0(0,4)  BFLYW(1,5,R,R)   BFLYI(2,6)  BFLYW(3,7,-R,R)
    BFLY0(8,12) BFLYW(9,13,R,R)  BFLYI(10,14) BFLYW(11,15,-R,R)
    BFLY0(0,8)  BFLYW(1,9,C8,S8) BFLYW(2,10,R,R) BFLYW(3,11,S8,C8)
    BFLYI(4,12) BFLYW(5,13,-S8,C8) BFLYW(6,14,-R,R) BFLYW(7,15,-C8,S8)
}

__device__ __forceinline__ int brev4(int v) {
    return ((v & 1) << 3) | ((v & 2) << 1) | ((v & 4) >> 1) | (v >> 3);
}

__global__ __launch_bounds__(NT) void istft_kernel(
    const float* __restrict__ x,   // [B, 1, 257, 6, 2] contiguous
    float* __restrict__ out)       // [B, 1, 600]
{
    const int b2   = blockIdx.x;   // batch-element pair
    const int tid  = threadIdx.x;
    const int lane = tid & 31;
    const int w    = tid >> 5;
    const int sub  = lane >> 4;    // frame-in-warp
    const int L    = lane & 15;
    const int fg   = 2 * w + sub;  // 0..11: global frame; elem = fg/6, t = fg%6

    // pool time-shared: Z [2][6][258] (3096) -> scratch [12][272] (3264)
    //                   -> fbuf [12][256] (3072)
    __shared__ __align__(16) float2 pool[3264];

    // ---- phase 1: staging + Hermitian half-size combine ----
    // Z[k]=E+iO, Z[256-k]=conj(E-iO) from bin pair (k, 256-k).
    {
        for (int i = tid; i < 774; i += NT) {
            const int e  = (i >= 387);
            const int ii = i - 387 * e;
            const float4* src = reinterpret_cast<const float4*>(
                x + ((size_t)b2 * 2 + e) * 3084);
            float2* Zb = pool + e * 1548;
            if (ii < 381) {
                const int k  = ii / 3 + 1;          // 1..127
                const int rr = ii - (k - 1) * 3;
                const float4 A  = src[k * 3 + rr];
                const float4 Bv = src[(256 - k) * 3 + rr];
                float s, c;                          // e^{i*pi*k/256}
                __sincosf((float)k * (PI_F / 256.0f), &s, &c);
                #pragma unroll
                for (int f = 0; f < 2; f++) {
                    const float Xr = f ? A.z : A.x,   Xi = f ? A.w : A.y;
                    const float Yr = f ? Bv.z : Bv.x, Yi = f ? Bv.w : Bv.y;
                    const float Er = 0.5f * (Xr + Yr), Ei = 0.5f * (Xi - Yi);
                    const float Dr = 0.5f * (Xr - Yr), Di = 0.5f * (Xi + Yi);
                    const float Or = Dr * c - Di * s;
                    const float Oi = Dr * s + Di * c;
                    const int tt = 2 * rr + f;
                    Zb[tt * 258 + k]       = make_float2(Er - Oi, Ei + Or);
                    Zb[tt * 258 + 256 - k] = make_float2(Er + Oi, Or - Ei);
                }
            } else if (ii < 384) {
                const int rr = ii - 381;
                const float4 A  = src[rr];               // bin 0
                const float4 Bv = src[256 * 3 + rr];     // bin 256 (Nyquist)
                Zb[(2 * rr)     * 258] = make_float2(0.5f * (A.x + Bv.x), 0.5f * (A.x - Bv.x));
                Zb[(2 * rr + 1) * 258] = make_float2(0.5f * (A.z + Bv.z), 0.5f * (A.z - Bv.z));
            } else {
                const int rr = ii - 384;
                const float4 A = src[128 * 3 + rr];      // bin 128 self-paired
                Zb[(2 * rr)     * 258 + 128] = make_float2(A.x, -A.y);
                Zb[(2 * rr + 1) * 258 + 128] = make_float2(A.z, -A.w);
            }
        }
    }
    __syncthreads();

    // ---- phase 2: load Z[L + 16*n2] into bit-reversed slots ----
    float Br[16], Bi[16];
    {
        const int e = fg >= 6 ? 1 : 0;
        const float2* rowZ = pool + e * 1548 + (fg - 6 * e) * 258;
        #pragma unroll
        for (int s = 0; s < 16; s++) {
            const float2 z = rowZ[L + (brev4(s) << 4)];
            Br[s] = z.x; Bi[s] = z.y;
        }
    }
    __syncthreads();               // Z dead -> pool reusable as scratch

    // ---- inner 16-pt IFFT over n2 (k1 output, natural order) ----
    ifft16(Br, Bi);

    // ---- four-step twiddle e^{+i*pi*L*k1/128} via recurrence ----
    {
        float wc, ws;
        __sincosf((float)L * (PI_F / 128.0f), &ws, &wc);
        float cc = wc, cs = ws;
        #pragma unroll
        for (int k1 = 1; k1 < 16; k1++) {
            const float br = Br[k1] * cc - Bi[k1] * cs;
            Bi[k1] = Br[k1] * cs + Bi[k1] * cc;
            Br[k1] = br;
            const float nc = cc * wc - cs * ws;
            cs = cc * ws + cs * wc;
            cc = nc;
        }
    }

    // ---- 16x16 transpose through shared (pitch 17, conflict-free) ----
    {
        float2* scr = pool + fg * 272;
        #pragma unroll
        for (int k1 = 0; k1 < 16; k1++)
            scr[L * 17 + k1] = make_float2(Br[k1], Bi[k1]);
        __syncwarp();
        #pragma unroll
        for (int s = 0; s < 16; s++) {
            const float2 z = scr[brev4(s) * 17 + L];   // row n1, column k1=L
            Br[s] = z.x; Bi[s] = z.y;
        }
    }
    __syncthreads();               // scratch dead -> pool reusable as fbuf

    // ---- outer 16-pt IFFT over n1: slot k2 = X[L + 16*k2] ----
    ifft16(Br, Bi);

    // ---- store frame buffer (natural order) ----
    {
        float2* fb = pool + fg * 256;
        #pragma unroll
        for (int k2 = 0; k2 < 16; k2++)
            fb[L + (k2 << 4)] = make_float2(Br[k2], Bi[k2]);
    }
    __syncthreads();

    // ---- paired OLA: outputs (2m, 2m+1) share one float2 per frame ----
    // p = 128q + r (r even); frame q-k at float2 index base - 192k.
    // cos(pi(r+128k)/256) = {c,-s,-c,s}; odd-sample window by angle addition.
    const float2* fb = pool;
    const float cd = 0.99992470183914454093f;   // cos(pi/256)
    const float sd = 0.01227153828571992608f;   // sin(pi/256)
    for (int mm = tid; mm < 600; mm += NT) {
        const int e = (mm >= 300);
        const int m = mm - 300 * e;
        const int p = 2 * m + 256;
        const int q = p >> 7;                   // 2..6
        const int r = p & 127;                  // even
        float s, c;
        __sincosf((float)r * (PI_F / 256.0f), &s, &c);
        const float c1 = c * cd - s * sd;
        const float s1 = s * cd + c * sd;
        const float w0 = 0.5f - 0.5f * c,  u0 = 0.5f - 0.5f * c1;
        const float w1 = 0.5f + 0.5f * s,  u1 = 0.5f + 0.5f * s1;
        const float w2 = 0.5f + 0.5f * c,  u2 = 0.5f + 0.5f * c1;
        const float w3 = 0.5f - 0.5f * s,  u3 = 0.5f - 0.5f * s1;
        const int base = ((e * 6 + q) << 8) + (r >> 1);

        const float2 v1 = fb[base - 192];
        const float2 v2 = fb[base - 384];
        float acc0 = w1 * v1.x + w2 * v2.x;
        float acc1 = u1 * v1.y + u2 * v2.y;
        float env0 = w1 * w1 + w2 * w2;
        float env1 = u1 * u1 + u2 * u2;
        if (q <= 5) {
            const float2 v0 = fb[base];
            acc0 = fmaf(w0, v0.x, acc0); env0 = fmaf(w0, w0, env0);
            acc1 = fmaf(u0, v0.y, acc1); env1 = fmaf(u0, u0, env1);
        }
        if (q >= 3) {
            const float2 v3 = fb[base - 576];
            acc0 = fmaf(w3, v3.x, acc0); env0 = fmaf(w3, w3, env0);
            acc1 = fmaf(u3, v3.y, acc1); env1 = fmaf(u3, u3, env1);
        }
        float2 o;
        o.x = __fdividef(acc0, 256.0f * env0);
        o.y = __fdividef(acc1, 256.0f * env1);
        *reinterpret_cast<float2*>(out + ((size_t)b2 * 2 + e) * 600 + 2 * m) = o;
    }
}

extern "C" void kernel_launch(void* const* d_in, const int* in_sizes, int n_in,
                              void* d_out, int out_size) {
    (void)in_sizes; (void)n_in; (void)out_size;
    const float* x = (const float*)d_in[0];
    float* out = (float*)d_out;
    istft_kernel<<<4096, NT>>>(x, out);
}